// round 10
// baseline (speedup 1.0000x reference)
#include <cuda_runtime.h>
#include <cuda_bf16.h>
#include <cstdint>

// Problem constants (shapes fixed by the dataset)
#define N_NODES_MAX 100000
#define D 64
#define OUT 64
#define LN_EPS 1e-5f

// Scratch (device globals — no allocs allowed)
__device__ __align__(16) float g_nsum[N_NODES_MAX * D];       // scatter accumulator
__device__ __align__(16) float g_partial[N_NODES_MAX * OUT];  // x@W1 + b

#define TILE_N 128
#define NTHR   256

// ---------------------------------------------------------------------------
// Kernel 1 (fused): block-role split.
//   role gemm1  (bid % 4 == 0, tile = bid/4 < n_tiles):
//       partial[tile] = x[tile] @ W[0:64] + b      (K=64, R8-style 8x4 tile)
//   role scatter (other blocks): edge scatter-add into g_nsum (red.v4)
// Every wave carries ~3:1 scatter:gemm blocks -> gemm FMA work hides under
// the L2-bandwidth-bound scatter.
// ---------------------------------------------------------------------------
__global__ void __launch_bounds__(NTHR, 3) fused_scatter_gemm1_kernel(
    const float4* __restrict__ x4,
    const void*   __restrict__ ei_raw,
    const float4* __restrict__ W4,
    const float*  __restrict__ b,
    int n_edges, int n_nodes, int n_tiles, int n_scat_blocks) {

    extern __shared__ char smem_raw[];
    const int bid = blockIdx.x;
    const int tid = threadIdx.x;

    const int quarter = bid >> 2;
    const bool is_gemm = ((bid & 3) == 0) && (quarter < n_tiles);

    if (is_gemm) {
        // ---------------- gemm1 role: partial = x @ W1 + b ----------------
        float* Ash = reinterpret_cast<float*>(smem_raw);              // [64][128] 32KB
        float* Wsh = reinterpret_cast<float*>(smem_raw + 64*128*4);   // [64][64]  16KB

        const int tx = tid & 15;   // outs 4tx..4tx+3
        const int ty = tid >> 4;   // nodes 8ty..8ty+7
        const int node_base = quarter * TILE_N;

        // stage W1 = W rows 0..63 (first 1024 float4s of W)
        {
            float4* Wsh4 = reinterpret_cast<float4*>(Wsh);
            #pragma unroll
            for (int i = tid; i < 64 * 64 / 4; i += NTHR) Wsh4[i] = W4[i];
        }
        // stage A transposed: Ash[k][n] = x[node_base+n][k], k<64
        {
            #pragma unroll
            for (int it = 0; it < 8; it++) {
                int idx = it * NTHR + tid;     // 0..2047
                int n = idx & 127;
                int r = idx >> 7;              // k-quad 0..15
                int gn = node_base + n;
                float4 v = make_float4(0.f, 0.f, 0.f, 0.f);
                if (gn < n_nodes) v = x4[(long long)gn * 16 + r];
                int k0 = 4 * r;
                Ash[(k0 + 0) * 128 + n] = v.x;
                Ash[(k0 + 1) * 128 + n] = v.y;
                Ash[(k0 + 2) * 128 + n] = v.z;
                Ash[(k0 + 3) * 128 + n] = v.w;
            }
        }
        __syncthreads();

        unsigned long long acc[4][4];
        #pragma unroll
        for (int i = 0; i < 4; i++)
            #pragma unroll
            for (int j = 0; j < 4; j++) acc[i][j] = 0ull;

        const unsigned long long* ab =
            reinterpret_cast<const unsigned long long*>(Ash + 8 * ty);
        const float* wb = Wsh + 4 * tx;

        #pragma unroll 8
        for (int k = 0; k < 64; k++) {
            ulonglong2 a01 = *reinterpret_cast<const ulonglong2*>(ab + k * 64);
            ulonglong2 a23 = *reinterpret_cast<const ulonglong2*>(ab + k * 64 + 2);
            float4 wv = *reinterpret_cast<const float4*>(wb + k * 64);
            unsigned long long wd[4];
            asm("mov.b64 %0, {%1, %1};" : "=l"(wd[0]) : "f"(wv.x));
            asm("mov.b64 %0, {%1, %1};" : "=l"(wd[1]) : "f"(wv.y));
            asm("mov.b64 %0, {%1, %1};" : "=l"(wd[2]) : "f"(wv.z));
            asm("mov.b64 %0, {%1, %1};" : "=l"(wd[3]) : "f"(wv.w));
            unsigned long long ap[4] = {a01.x, a01.y, a23.x, a23.y};
            #pragma unroll
            for (int i = 0; i < 4; i++) {
                asm("fma.rn.f32x2 %0, %1, %2, %0;" : "+l"(acc[i][0]) : "l"(ap[i]), "l"(wd[0]));
                asm("fma.rn.f32x2 %0, %1, %2, %0;" : "+l"(acc[i][1]) : "l"(ap[i]), "l"(wd[1]));
                asm("fma.rn.f32x2 %0, %1, %2, %0;" : "+l"(acc[i][2]) : "l"(ap[i]), "l"(wd[2]));
                asm("fma.rn.f32x2 %0, %1, %2, %0;" : "+l"(acc[i][3]) : "l"(ap[i]), "l"(wd[3]));
            }
        }

        // epilogue: + bias, store partial
        const float4 bj = reinterpret_cast<const float4*>(b)[tx];
        const float bja[4] = {bj.x, bj.y, bj.z, bj.w};
        float4* partial4 = reinterpret_cast<float4*>(g_partial);

        #pragma unroll
        for (int i = 0; i < 4; i++) {
            float lo[4], hi[4];
            #pragma unroll
            for (int j = 0; j < 4; j++) {
                lo[j] = __uint_as_float((unsigned)(acc[i][j] & 0xffffffffull)) + bja[j];
                hi[j] = __uint_as_float((unsigned)(acc[i][j] >> 32))           + bja[j];
            }
            int gn0 = node_base + 8 * ty + 2 * i;
            if (gn0 < n_nodes)
                partial4[(long long)gn0 * 16 + tx] = make_float4(lo[0], lo[1], lo[2], lo[3]);
            if (gn0 + 1 < n_nodes)
                partial4[(long long)(gn0 + 1) * 16 + tx] = make_float4(hi[0], hi[1], hi[2], hi[3]);
        }
    } else {
        // ---------------- scatter role ----------------
        const long long* ei64 = reinterpret_cast<const long long*>(ei_raw);
        const int*       ei32 = reinterpret_cast<const int*>(ei_raw);

        // per-block dtype detection (first 256 int64 words, L2-cached)
        int bad = 0;
        {
            int nw = n_edges / 2;
            if (nw > 256) nw = 256;
            if (tid < nw) {
                long long v = ei64[tid];
                bad = (v < 0 || v >= (long long)n_nodes) ? 1 : 0;
            }
        }
        const int is64 = !__syncthreads_or(bad);

        // dense scatter-block index
        int g_before = (bid + 3) >> 2;
        if (g_before > n_tiles) g_before = n_tiles;
        const int sbid = bid - g_before;

        const int t   = sbid * NTHR + tid;
        const int sub = t & 15;
        int e = t >> 4;
        const int estride = (n_scat_blocks * NTHR) >> 4;
        float4* __restrict__ nsum4 = reinterpret_cast<float4*>(g_nsum);

        if (is64) {
            for (; e < n_edges; e += estride) {
                long long row = ei64[e];
                long long col = ei64[n_edges + e];
                float4 v = x4[row * 16 + sub];
                float4* dst = &nsum4[col * 16 + sub];
                asm volatile("red.global.add.v4.f32 [%0], {%1, %2, %3, %4};"
                             :: "l"(dst), "f"(v.x), "f"(v.y), "f"(v.z), "f"(v.w)
                             : "memory");
            }
        } else {
            for (; e < n_edges; e += estride) {
                long long row = ei32[e];
                long long col = ei32[n_edges + e];
                float4 v = x4[row * 16 + sub];
                float4* dst = &nsum4[col * 16 + sub];
                asm volatile("red.global.add.v4.f32 [%0], {%1, %2, %3, %4};"
                             :: "l"(dst), "f"(v.x), "f"(v.y), "f"(v.z), "f"(v.w)
                             : "memory");
            }
        }
    }
}

// ---------------------------------------------------------------------------
// Kernel 2: h = nsum @ W2 + partial, then LayerNorm.  K=64.
// 8x4 node-packed tile (R8-proven), W2 via L1 (__ldg), A-only smem (32KB).
// ---------------------------------------------------------------------------
__global__ void __launch_bounds__(NTHR, 3) gemm2_ln_kernel(
    const float4* __restrict__ W4,
    const float*  __restrict__ gamma,
    const float*  __restrict__ beta,
    float4* __restrict__ out4,
    int n_nodes) {

    extern __shared__ char smem_raw[];
    float* Ash = reinterpret_cast<float*>(smem_raw);   // [64][128] = 32KB

    const int tid = threadIdx.x;
    const int tx  = tid & 15;
    const int ty  = tid >> 4;
    const int node_base = blockIdx.x * TILE_N;

    // stage A transposed from nsum: Ash[k][n] = nsum[node_base+n][k], k<64
    {
        const float4* nsum4 = reinterpret_cast<const float4*>(g_nsum);
        #pragma unroll
        for (int it = 0; it < 8; it++) {
            int idx = it * NTHR + tid;
            int n = idx & 127;
            int r = idx >> 7;              // k-quad 0..15
            int gn = node_base + n;
            float4 v = make_float4(0.f, 0.f, 0.f, 0.f);
            if (gn < n_nodes) v = nsum4[(long long)gn * 16 + r];
            int k0 = 4 * r;
            Ash[(k0 + 0) * 128 + n] = v.x;
            Ash[(k0 + 1) * 128 + n] = v.y;
            Ash[(k0 + 2) * 128 + n] = v.z;
            Ash[(k0 + 3) * 128 + n] = v.w;
        }
    }
    __syncthreads();

    unsigned long long acc[4][4];
    #pragma unroll
    for (int i = 0; i < 4; i++)
        #pragma unroll
        for (int j = 0; j < 4; j++) acc[i][j] = 0ull;

    const unsigned long long* ab =
        reinterpret_cast<const unsigned long long*>(Ash + 8 * ty);
    const float4* wg = W4 + 64 * 16 + tx;   // W rows 64..127

    #pragma unroll 8
    for (int k = 0; k < 64; k++) {
        ulonglong2 a01 = *reinterpret_cast<const ulonglong2*>(ab + k * 64);
        ulonglong2 a23 = *reinterpret_cast<const ulonglong2*>(ab + k * 64 + 2);
        float4 wv = __ldg(wg + k * 16);
        unsigned long long wd[4];
        asm("mov.b64 %0, {%1, %1};" : "=l"(wd[0]) : "f"(wv.x));
        asm("mov.b64 %0, {%1, %1};" : "=l"(wd[1]) : "f"(wv.y));
        asm("mov.b64 %0, {%1, %1};" : "=l"(wd[2]) : "f"(wv.z));
        asm("mov.b64 %0, {%1, %1};" : "=l"(wd[3]) : "f"(wv.w));
        unsigned long long ap[4] = {a01.x, a01.y, a23.x, a23.y};
        #pragma unroll
        for (int i = 0; i < 4; i++) {
            asm("fma.rn.f32x2 %0, %1, %2, %0;" : "+l"(acc[i][0]) : "l"(ap[i]), "l"(wd[0]));
            asm("fma.rn.f32x2 %0, %1, %2, %0;" : "+l"(acc[i][1]) : "l"(ap[i]), "l"(wd[1]));
            asm("fma.rn.f32x2 %0, %1, %2, %0;" : "+l"(acc[i][2]) : "l"(ap[i]), "l"(wd[2]));
            asm("fma.rn.f32x2 %0, %1, %2, %0;" : "+l"(acc[i][3]) : "l"(ap[i]), "l"(wd[3]));
        }
    }

    // epilogue: + partial, LayerNorm, store
    const float4 gj = reinterpret_cast<const float4*>(gamma)[tx];
    const float4 ej = reinterpret_cast<const float4*>(beta)[tx];
    const float4* partial4 = reinterpret_cast<const float4*>(g_partial);

    float val[8][4];   // [node 0..7][out 0..3]
    #pragma unroll
    for (int i = 0; i < 4; i++) {
        int gn0 = node_base + 8 * ty + 2 * i;
        float4 p0 = (gn0     < n_nodes) ? partial4[(long long)gn0 * 16 + tx]
                                        : make_float4(0.f, 0.f, 0.f, 0.f);
        float4 p1 = (gn0 + 1 < n_nodes) ? partial4[(long long)(gn0 + 1) * 16 + tx]
                                        : make_float4(0.f, 0.f, 0.f, 0.f);
        const float pa0[4] = {p0.x, p0.y, p0.z, p0.w};
        const float pa1[4] = {p1.x, p1.y, p1.z, p1.w};
        #pragma unroll
        for (int j = 0; j < 4; j++) {
            val[2 * i][j]     = __uint_as_float((unsigned)(acc[i][j] & 0xffffffffull)) + pa0[j];
            val[2 * i + 1][j] = __uint_as_float((unsigned)(acc[i][j] >> 32))           + pa1[j];
        }
    }

    float s[8], ss[8];
    #pragma unroll
    for (int i = 0; i < 8; i++) {
        s[i]  = val[i][0] + val[i][1] + val[i][2] + val[i][3];
        ss[i] = val[i][0] * val[i][0] + val[i][1] * val[i][1]
              + val[i][2] * val[i][2] + val[i][3] * val[i][3];
    }
    #pragma unroll
    for (int m = 1; m < 16; m <<= 1) {
        #pragma unroll
        for (int i = 0; i < 8; i++) {
            s[i]  += __shfl_xor_sync(0xFFFFFFFFu, s[i],  m);
            ss[i] += __shfl_xor_sync(0xFFFFFFFFu, ss[i], m);
        }
    }

    const float inv64 = 1.0f / 64.0f;
    #pragma unroll
    for (int i = 0; i < 8; i++) {
        float mu  = s[i] * inv64;
        float var = ss[i] * inv64 - mu * mu;
        float rs  = rsqrtf(var + LN_EPS);
        int gn = node_base + 8 * ty + i;
        if (gn < n_nodes) {
            float4 o;
            o.x = (val[i][0] - mu) * rs * gj.x + ej.x;
            o.y = (val[i][1] - mu) * rs * gj.y + ej.y;
            o.z = (val[i][2] - mu) * rs * gj.z + ej.z;
            o.w = (val[i][3] - mu) * rs * gj.w + ej.w;
            out4[(long long)gn * 16 + tx] = o;
        }
    }
}

// ---------------------------------------------------------------------------
// launch
// ---------------------------------------------------------------------------
extern "C" void kernel_launch(void* const* d_in, const int* in_sizes, int n_in,
                              void* d_out, int out_size) {
    const float* x     = (const float*)d_in[0];
    const void*  ei    = d_in[1];
    const float* W     = (const float*)d_in[2];
    const float* b     = (const float*)d_in[3];
    const float* gamma = (const float*)d_in[4];
    const float* beta  = (const float*)d_in[5];
    float* out = (float*)d_out;

    const int n_nodes = in_sizes[0] / D;      // 100000
    const int n_edges = in_sizes[1] / 2;      // 1000000

    cudaFuncSetAttribute(fused_scatter_gemm1_kernel,
                         cudaFuncAttributeMaxDynamicSharedMemorySize, 49152);
    cudaFuncSetAttribute(gemm2_ln_kernel,
                         cudaFuncAttributeMaxDynamicSharedMemorySize, 32768);

    // 0: zero accumulator via memset node
    static void* nsum_ptr = nullptr;
    if (!nsum_ptr) cudaGetSymbolAddress(&nsum_ptr, g_nsum);
    cudaMemsetAsync(nsum_ptr, 0, (size_t)n_nodes * D * sizeof(float), 0);

    // 1: fused scatter + x@W1 (role mix 3:1 per wave)
    const int n_tiles = (n_nodes + TILE_N - 1) / TILE_N;   // 782
    const int grid = 4 * n_tiles;                          // 3128
    const int n_scat_blocks = grid - n_tiles;              // 2346
    fused_scatter_gemm1_kernel<<<grid, NTHR, 49152>>>(
        (const float4*)x, ei, (const float4*)W, b,
        n_edges, n_nodes, n_tiles, n_scat_blocks);

    // 2: nsum@W2 + partial, LayerNorm
    gemm2_ln_kernel<<<n_tiles, NTHR, 32768>>>(
        (const float4*)W, gamma, beta, (float4*)out, n_nodes);
}

// round 11
// speedup vs baseline: 1.4155x; 1.4155x over previous
#include <cuda_runtime.h>
#include <cuda_bf16.h>
#include <cstdint>

// Problem constants (shapes fixed by the dataset)
#define N_NODES_MAX 100000
#define D 64
#define OUT 64
#define LN_EPS 1e-5f

// Scratch (device globals — no allocs allowed)
__device__ __align__(16) float g_nsum[N_NODES_MAX * D];       // scatter accumulator
__device__ __align__(16) float g_partial[N_NODES_MAX * OUT];  // x@W1 + b

#define TILE_N 128
#define NTHR   256

// ---------------------------------------------------------------------------
// Kernel S: scatter-add (R8-proven). 16 lanes/edge, red.global.add.v4.f32.
// Per-block dtype detection (proven harmless).
// ---------------------------------------------------------------------------
__global__ void __launch_bounds__(256) scatter_kernel(
    const float4* __restrict__ x4,
    const void* __restrict__ ei_raw,
    int n_edges, int n_nodes) {

    const long long* ei64 = reinterpret_cast<const long long*>(ei_raw);
    const int*       ei32 = reinterpret_cast<const int*>(ei_raw);

    int bad = 0;
    {
        int nw = n_edges / 2;
        if (nw > 256) nw = 256;
        if ((int)threadIdx.x < nw) {
            long long v = ei64[threadIdx.x];
            bad = (v < 0 || v >= (long long)n_nodes) ? 1 : 0;
        }
    }
    const int is64 = !__syncthreads_or(bad);

    const int t   = blockIdx.x * blockDim.x + threadIdx.x;
    const int sub = t & 15;
    int e = t >> 4;
    const int estride = (gridDim.x * blockDim.x) >> 4;
    float4* __restrict__ nsum4 = reinterpret_cast<float4*>(g_nsum);

    if (is64) {
        for (; e < n_edges; e += estride) {
            long long row = ei64[e];
            long long col = ei64[n_edges + e];
            float4 v = x4[row * 16 + sub];
            float4* dst = &nsum4[col * 16 + sub];
            asm volatile("red.global.add.v4.f32 [%0], {%1, %2, %3, %4};"
                         :: "l"(dst), "f"(v.x), "f"(v.y), "f"(v.z), "f"(v.w)
                         : "memory");
        }
    } else {
        for (; e < n_edges; e += estride) {
            long long row = ei32[e];
            long long col = ei32[n_edges + e];
            float4 v = x4[row * 16 + sub];
            float4* dst = &nsum4[col * 16 + sub];
            asm volatile("red.global.add.v4.f32 [%0], {%1, %2, %3, %4};"
                         :: "l"(dst), "f"(v.x), "f"(v.y), "f"(v.z), "f"(v.w)
                         : "memory");
        }
    }
}

// ---------------------------------------------------------------------------
// Kernel G1: partial = x @ W1 + b   (K=64, 8x4 node-packed tile, W1 in smem)
// Runs CONCURRENTLY with the scatter (separate captured stream).
// ---------------------------------------------------------------------------
__global__ void __launch_bounds__(NTHR, 3) gemm1_kernel(
    const float4* __restrict__ x4,
    const float4* __restrict__ W4,
    const float*  __restrict__ b,
    int n_nodes) {

    extern __shared__ char smem_raw[];
    float* Ash = reinterpret_cast<float*>(smem_raw);              // [64][128] 32KB
    float* Wsh = reinterpret_cast<float*>(smem_raw + 64*128*4);   // [64][64]  16KB

    const int tid = threadIdx.x;
    const int tx = tid & 15;
    const int ty = tid >> 4;
    const int node_base = blockIdx.x * TILE_N;

    // stage W1 = W rows 0..63
    {
        float4* Wsh4 = reinterpret_cast<float4*>(Wsh);
        #pragma unroll
        for (int i = tid; i < 64 * 64 / 4; i += NTHR) Wsh4[i] = W4[i];
    }
    // stage A transposed: Ash[k][n] = x[node_base+n][k], k<64
    {
        #pragma unroll
        for (int it = 0; it < 8; it++) {
            int idx = it * NTHR + tid;
            int n = idx & 127;
            int r = idx >> 7;              // k-quad 0..15
            int gn = node_base + n;
            float4 v = make_float4(0.f, 0.f, 0.f, 0.f);
            if (gn < n_nodes) v = x4[(long long)gn * 16 + r];
            int k0 = 4 * r;
            Ash[(k0 + 0) * 128 + n] = v.x;
            Ash[(k0 + 1) * 128 + n] = v.y;
            Ash[(k0 + 2) * 128 + n] = v.z;
            Ash[(k0 + 3) * 128 + n] = v.w;
        }
    }
    __syncthreads();

    unsigned long long acc[4][4];
    #pragma unroll
    for (int i = 0; i < 4; i++)
        #pragma unroll
        for (int j = 0; j < 4; j++) acc[i][j] = 0ull;

    const unsigned long long* ab =
        reinterpret_cast<const unsigned long long*>(Ash + 8 * ty);
    const float* wb = Wsh + 4 * tx;

    #pragma unroll 8
    for (int k = 0; k < 64; k++) {
        ulonglong2 a01 = *reinterpret_cast<const ulonglong2*>(ab + k * 64);
        ulonglong2 a23 = *reinterpret_cast<const ulonglong2*>(ab + k * 64 + 2);
        float4 wv = *reinterpret_cast<const float4*>(wb + k * 64);
        unsigned long long wd[4];
        asm("mov.b64 %0, {%1, %1};" : "=l"(wd[0]) : "f"(wv.x));
        asm("mov.b64 %0, {%1, %1};" : "=l"(wd[1]) : "f"(wv.y));
        asm("mov.b64 %0, {%1, %1};" : "=l"(wd[2]) : "f"(wv.z));
        asm("mov.b64 %0, {%1, %1};" : "=l"(wd[3]) : "f"(wv.w));
        unsigned long long ap[4] = {a01.x, a01.y, a23.x, a23.y};
        #pragma unroll
        for (int i = 0; i < 4; i++) {
            asm("fma.rn.f32x2 %0, %1, %2, %0;" : "+l"(acc[i][0]) : "l"(ap[i]), "l"(wd[0]));
            asm("fma.rn.f32x2 %0, %1, %2, %0;" : "+l"(acc[i][1]) : "l"(ap[i]), "l"(wd[1]));
            asm("fma.rn.f32x2 %0, %1, %2, %0;" : "+l"(acc[i][2]) : "l"(ap[i]), "l"(wd[2]));
            asm("fma.rn.f32x2 %0, %1, %2, %0;" : "+l"(acc[i][3]) : "l"(ap[i]), "l"(wd[3]));
        }
    }

    const float4 bj = reinterpret_cast<const float4*>(b)[tx];
    const float bja[4] = {bj.x, bj.y, bj.z, bj.w};
    float4* partial4 = reinterpret_cast<float4*>(g_partial);

    #pragma unroll
    for (int i = 0; i < 4; i++) {
        float lo[4], hi[4];
        #pragma unroll
        for (int j = 0; j < 4; j++) {
            lo[j] = __uint_as_float((unsigned)(acc[i][j] & 0xffffffffull)) + bja[j];
            hi[j] = __uint_as_float((unsigned)(acc[i][j] >> 32))           + bja[j];
        }
        int gn0 = node_base + 8 * ty + 2 * i;
        if (gn0 < n_nodes)
            partial4[(long long)gn0 * 16 + tx] = make_float4(lo[0], lo[1], lo[2], lo[3]);
        if (gn0 + 1 < n_nodes)
            partial4[(long long)(gn0 + 1) * 16 + tx] = make_float4(hi[0], hi[1], hi[2], hi[3]);
    }
}

// ---------------------------------------------------------------------------
// Kernel G2: h = nsum @ W2 + partial, then LayerNorm.  K=64.
// (measured 34 us in R10; validated)
// ---------------------------------------------------------------------------
__global__ void __launch_bounds__(NTHR, 3) gemm2_ln_kernel(
    const float4* __restrict__ W4,
    const float*  __restrict__ gamma,
    const float*  __restrict__ beta,
    float4* __restrict__ out4,
    int n_nodes) {

    extern __shared__ char smem_raw[];
    float* Ash = reinterpret_cast<float*>(smem_raw);   // [64][128] = 32KB

    const int tid = threadIdx.x;
    const int tx  = tid & 15;
    const int ty  = tid >> 4;
    const int node_base = blockIdx.x * TILE_N;

    {
        const float4* nsum4 = reinterpret_cast<const float4*>(g_nsum);
        #pragma unroll
        for (int it = 0; it < 8; it++) {
            int idx = it * NTHR + tid;
            int n = idx & 127;
            int r = idx >> 7;
            int gn = node_base + n;
            float4 v = make_float4(0.f, 0.f, 0.f, 0.f);
            if (gn < n_nodes) v = nsum4[(long long)gn * 16 + r];
            int k0 = 4 * r;
            Ash[(k0 + 0) * 128 + n] = v.x;
            Ash[(k0 + 1) * 128 + n] = v.y;
            Ash[(k0 + 2) * 128 + n] = v.z;
            Ash[(k0 + 3) * 128 + n] = v.w;
        }
    }
    __syncthreads();

    unsigned long long acc[4][4];
    #pragma unroll
    for (int i = 0; i < 4; i++)
        #pragma unroll
        for (int j = 0; j < 4; j++) acc[i][j] = 0ull;

    const unsigned long long* ab =
        reinterpret_cast<const unsigned long long*>(Ash + 8 * ty);
    const float4* wg = W4 + 64 * 16 + tx;   // W rows 64..127

    #pragma unroll 8
    for (int k = 0; k < 64; k++) {
        ulonglong2 a01 = *reinterpret_cast<const ulonglong2*>(ab + k * 64);
        ulonglong2 a23 = *reinterpret_cast<const ulonglong2*>(ab + k * 64 + 2);
        float4 wv = __ldg(wg + k * 16);
        unsigned long long wd[4];
        asm("mov.b64 %0, {%1, %1};" : "=l"(wd[0]) : "f"(wv.x));
        asm("mov.b64 %0, {%1, %1};" : "=l"(wd[1]) : "f"(wv.y));
        asm("mov.b64 %0, {%1, %1};" : "=l"(wd[2]) : "f"(wv.z));
        asm("mov.b64 %0, {%1, %1};" : "=l"(wd[3]) : "f"(wv.w));
        unsigned long long ap[4] = {a01.x, a01.y, a23.x, a23.y};
        #pragma unroll
        for (int i = 0; i < 4; i++) {
            asm("fma.rn.f32x2 %0, %1, %2, %0;" : "+l"(acc[i][0]) : "l"(ap[i]), "l"(wd[0]));
            asm("fma.rn.f32x2 %0, %1, %2, %0;" : "+l"(acc[i][1]) : "l"(ap[i]), "l"(wd[1]));
            asm("fma.rn.f32x2 %0, %1, %2, %0;" : "+l"(acc[i][2]) : "l"(ap[i]), "l"(wd[2]));
            asm("fma.rn.f32x2 %0, %1, %2, %0;" : "+l"(acc[i][3]) : "l"(ap[i]), "l"(wd[3]));
        }
    }

    const float4 gj = reinterpret_cast<const float4*>(gamma)[tx];
    const float4 ej = reinterpret_cast<const float4*>(beta)[tx];
    const float4* partial4 = reinterpret_cast<const float4*>(g_partial);

    float val[8][4];
    #pragma unroll
    for (int i = 0; i < 4; i++) {
        int gn0 = node_base + 8 * ty + 2 * i;
        float4 p0 = (gn0     < n_nodes) ? partial4[(long long)gn0 * 16 + tx]
                                        : make_float4(0.f, 0.f, 0.f, 0.f);
        float4 p1 = (gn0 + 1 < n_nodes) ? partial4[(long long)(gn0 + 1) * 16 + tx]
                                        : make_float4(0.f, 0.f, 0.f, 0.f);
        const float pa0[4] = {p0.x, p0.y, p0.z, p0.w};
        const float pa1[4] = {p1.x, p1.y, p1.z, p1.w};
        #pragma unroll
        for (int j = 0; j < 4; j++) {
            val[2 * i][j]     = __uint_as_float((unsigned)(acc[i][j] & 0xffffffffull)) + pa0[j];
            val[2 * i + 1][j] = __uint_as_float((unsigned)(acc[i][j] >> 32))           + pa1[j];
        }
    }

    float s[8], ss[8];
    #pragma unroll
    for (int i = 0; i < 8; i++) {
        s[i]  = val[i][0] + val[i][1] + val[i][2] + val[i][3];
        ss[i] = val[i][0] * val[i][0] + val[i][1] * val[i][1]
              + val[i][2] * val[i][2] + val[i][3] * val[i][3];
    }
    #pragma unroll
    for (int m = 1; m < 16; m <<= 1) {
        #pragma unroll
        for (int i = 0; i < 8; i++) {
            s[i]  += __shfl_xor_sync(0xFFFFFFFFu, s[i],  m);
            ss[i] += __shfl_xor_sync(0xFFFFFFFFu, ss[i], m);
        }
    }

    const float inv64 = 1.0f / 64.0f;
    #pragma unroll
    for (int i = 0; i < 8; i++) {
        float mu  = s[i] * inv64;
        float var = ss[i] * inv64 - mu * mu;
        float rs  = rsqrtf(var + LN_EPS);
        int gn = node_base + 8 * ty + i;
        if (gn < n_nodes) {
            float4 o;
            o.x = (val[i][0] - mu) * rs * gj.x + ej.x;
            o.y = (val[i][1] - mu) * rs * gj.y + ej.y;
            o.z = (val[i][2] - mu) * rs * gj.z + ej.z;
            o.w = (val[i][3] - mu) * rs * gj.w + ej.w;
            out4[(long long)gn * 16 + tx] = o;
        }
    }
}

// ---------------------------------------------------------------------------
// launch: graph-level fork/join.
//   main stream:  memset(nsum) -> scatter ----\
//   side stream:  gemm1 (x@W1+b, independent) --> join -> gemm2_ln
// ---------------------------------------------------------------------------
extern "C" void kernel_launch(void* const* d_in, const int* in_sizes, int n_in,
                              void* d_out, int out_size) {
    const float* x     = (const float*)d_in[0];
    const void*  ei    = d_in[1];
    const float* W     = (const float*)d_in[2];
    const float* b     = (const float*)d_in[3];
    const float* gamma = (const float*)d_in[4];
    const float* beta  = (const float*)d_in[5];
    float* out = (float*)d_out;

    const int n_nodes = in_sizes[0] / D;      // 100000
    const int n_edges = in_sizes[1] / 2;      // 1000000

    // one-time host-side resources (streams/events are not device allocs)
    static cudaStream_t s2 = nullptr;
    static cudaEvent_t e_fork = nullptr, e_join = nullptr;
    static void* nsum_ptr = nullptr;
    if (!s2) {
        cudaStreamCreateWithFlags(&s2, cudaStreamNonBlocking);
        cudaEventCreateWithFlags(&e_fork, cudaEventDisableTiming);
        cudaEventCreateWithFlags(&e_join, cudaEventDisableTiming);
        cudaGetSymbolAddress(&nsum_ptr, g_nsum);
        cudaFuncSetAttribute(gemm1_kernel,
                             cudaFuncAttributeMaxDynamicSharedMemorySize, 49152);
        cudaFuncSetAttribute(gemm2_ln_kernel,
                             cudaFuncAttributeMaxDynamicSharedMemorySize, 32768);
    }

    const int n_tiles = (n_nodes + TILE_N - 1) / TILE_N;   // 782

    // fork: side stream runs gemm1 concurrently with memset+scatter
    cudaEventRecord(e_fork, 0);
    cudaStreamWaitEvent(s2, e_fork, 0);
    gemm1_kernel<<<n_tiles, NTHR, 49152, s2>>>(
        (const float4*)x, (const float4*)W, b, n_nodes);
    cudaEventRecord(e_join, s2);

    // main stream: zero accumulator, then scatter
    cudaMemsetAsync(nsum_ptr, 0, (size_t)n_nodes * D * sizeof(float), 0);
    scatter_kernel<<<2368, 256>>>((const float4*)x, ei, n_edges, n_nodes);

    // join, then final gemm + LN
    cudaStreamWaitEvent(0, e_join, 0);
    gemm2_ln_kernel<<<n_tiles, NTHR, 32768>>>(
        (const float4*)W, gamma, beta, (float4*)out, n_nodes);
}

// round 12
// speedup vs baseline: 1.5005x; 1.0600x over previous
#include <cuda_runtime.h>
#include <cuda_bf16.h>
#include <cstdint>

// Problem constants (shapes fixed by the dataset)
#define N_NODES_MAX 100000
#define D 64
#define OUT 64
#define LN_EPS 1e-5f

// Scratch: neighbor_sum accumulator [N, D] — device global (no allocs allowed)
__device__ __align__(16) float g_nsum[N_NODES_MAX * D];

// ---------------------------------------------------------------------------
// Kernel 1: scatter-add, chunked unroll-4 for MLP.
// Each 16-lane group handles 4 CONSECUTIVE edges per iteration:
//   - index loads first (vectorized, independent)  -> 4x memory-level parallelism
//   - then 4 gathers, then 4 red.global.add.v4.f32
// Per-block dtype detection (proven harmless): int32-as-int64 high halves are
// ~uniform node indices; P(first 256 words all look valid) ~ 1e-1280.
// ---------------------------------------------------------------------------
__global__ void __launch_bounds__(256) scatter_kernel(
    const float4* __restrict__ x4,
    const void* __restrict__ ei_raw,
    int n_edges, int n_nodes) {

    const long long* ei64 = reinterpret_cast<const long long*>(ei_raw);
    const int*       ei32 = reinterpret_cast<const int*>(ei_raw);

    // per-block dtype detection
    int bad = 0;
    {
        int nw = n_edges / 2;
        if (nw > 256) nw = 256;
        if ((int)threadIdx.x < nw) {
            long long v = ei64[threadIdx.x];
            bad = (v < 0 || v >= (long long)n_nodes) ? 1 : 0;
        }
    }
    const int is64 = !__syncthreads_or(bad);

    const int t   = blockIdx.x * blockDim.x + threadIdx.x;
    const int sub = t & 15;
    const int grp = t >> 4;
    const int ngrp = (gridDim.x * blockDim.x) >> 4;
    float4* __restrict__ nsum4 = reinterpret_cast<float4*>(g_nsum);

    const int nchunks = n_edges >> 2;          // full chunks of 4 edges

    if (is64) {
        for (int c = grp; c < nchunks; c += ngrp) {
            const int e = c * 4;
            // batched, vectorized index loads (4 independent LDG.128)
            longlong2 r01 = *reinterpret_cast<const longlong2*>(ei64 + e);
            longlong2 r23 = *reinterpret_cast<const longlong2*>(ei64 + e + 2);
            longlong2 c01 = *reinterpret_cast<const longlong2*>(ei64 + n_edges + e);
            longlong2 c23 = *reinterpret_cast<const longlong2*>(ei64 + n_edges + e + 2);
            // 4 independent gathers
            float4 v0 = x4[r01.x * 16 + sub];
            float4 v1 = x4[r01.y * 16 + sub];
            float4 v2 = x4[r23.x * 16 + sub];
            float4 v3 = x4[r23.y * 16 + sub];
            asm volatile("red.global.add.v4.f32 [%0], {%1, %2, %3, %4};"
                         :: "l"(&nsum4[c01.x * 16 + sub]),
                            "f"(v0.x), "f"(v0.y), "f"(v0.z), "f"(v0.w) : "memory");
            asm volatile("red.global.add.v4.f32 [%0], {%1, %2, %3, %4};"
                         :: "l"(&nsum4[c01.y * 16 + sub]),
                            "f"(v1.x), "f"(v1.y), "f"(v1.z), "f"(v1.w) : "memory");
            asm volatile("red.global.add.v4.f32 [%0], {%1, %2, %3, %4};"
                         :: "l"(&nsum4[c23.x * 16 + sub]),
                            "f"(v2.x), "f"(v2.y), "f"(v2.z), "f"(v2.w) : "memory");
            asm volatile("red.global.add.v4.f32 [%0], {%1, %2, %3, %4};"
                         :: "l"(&nsum4[c23.y * 16 + sub]),
                            "f"(v3.x), "f"(v3.y), "f"(v3.z), "f"(v3.w) : "memory");
        }
        // tail (n_edges % 4 edges)
        for (int e = nchunks * 4 + grp; e < n_edges; e += ngrp) {
            long long row = ei64[e];
            long long col = ei64[n_edges + e];
            float4 v = x4[row * 16 + sub];
            asm volatile("red.global.add.v4.f32 [%0], {%1, %2, %3, %4};"
                         :: "l"(&nsum4[col * 16 + sub]),
                            "f"(v.x), "f"(v.y), "f"(v.z), "f"(v.w) : "memory");
        }
    } else {
        for (int c = grp; c < nchunks; c += ngrp) {
            const int e = c * 4;
            // batched, vectorized index loads (2 independent LDG.128)
            int4 rr = *reinterpret_cast<const int4*>(ei32 + e);
            int4 cc = *reinterpret_cast<const int4*>(ei32 + n_edges + e);
            float4 v0 = x4[(long long)rr.x * 16 + sub];
            float4 v1 = x4[(long long)rr.y * 16 + sub];
            float4 v2 = x4[(long long)rr.z * 16 + sub];
            float4 v3 = x4[(long long)rr.w * 16 + sub];
            asm volatile("red.global.add.v4.f32 [%0], {%1, %2, %3, %4};"
                         :: "l"(&nsum4[(long long)cc.x * 16 + sub]),
                            "f"(v0.x), "f"(v0.y), "f"(v0.z), "f"(v0.w) : "memory");
            asm volatile("red.global.add.v4.f32 [%0], {%1, %2, %3, %4};"
                         :: "l"(&nsum4[(long long)cc.y * 16 + sub]),
                            "f"(v1.x), "f"(v1.y), "f"(v1.z), "f"(v1.w) : "memory");
            asm volatile("red.global.add.v4.f32 [%0], {%1, %2, %3, %4};"
                         :: "l"(&nsum4[(long long)cc.z * 16 + sub]),
                            "f"(v2.x), "f"(v2.y), "f"(v2.z), "f"(v2.w) : "memory");
            asm volatile("red.global.add.v4.f32 [%0], {%1, %2, %3, %4};"
                         :: "l"(&nsum4[(long long)cc.w * 16 + sub]),
                            "f"(v3.x), "f"(v3.y), "f"(v3.z), "f"(v3.w) : "memory");
        }
        for (int e = nchunks * 4 + grp; e < n_edges; e += ngrp) {
            long long row = ei32[e];
            long long col = ei32[n_edges + e];
            float4 v = x4[row * 16 + sub];
            asm volatile("red.global.add.v4.f32 [%0], {%1, %2, %3, %4};"
                         :: "l"(&nsum4[col * 16 + sub]),
                            "f"(v.x), "f"(v.y), "f"(v.z), "f"(v.w) : "memory");
        }
    }
}

// ---------------------------------------------------------------------------
// Kernel 2: fused concat + Linear(128->64) + bias + LayerNorm.
// R8's proven gemm verbatim: 8x4 node-packed tile, W in smem, 96KB, K=128.
// ---------------------------------------------------------------------------
#define TILE_N 128
#define NTHR   256

__global__ void __launch_bounds__(NTHR, 2) gemm_ln_kernel(
    const float4* __restrict__ x4,
    const float*  __restrict__ W,
    const float*  __restrict__ b,
    const float*  __restrict__ gamma,
    const float*  __restrict__ beta,
    float4* __restrict__ out4,
    int n_nodes) {

    extern __shared__ char smem_raw[];
    float* Ash = reinterpret_cast<float*>(smem_raw);             // [128][128]
    float* Wsh = reinterpret_cast<float*>(smem_raw + 128 * 128 * 4); // [128][64]

    const int tid = threadIdx.x;
    const int tx  = tid & 15;   // outs 4tx..4tx+3
    const int ty  = tid >> 4;   // nodes 8ty..8ty+7
    const int node_base = blockIdx.x * TILE_N;

    // stage W (row-major [128][64])
    {
        const float4* W4 = reinterpret_cast<const float4*>(W);
        float4* Wsh4 = reinterpret_cast<float4*>(Wsh);
        #pragma unroll
        for (int i = tid; i < 128 * 64 / 4; i += NTHR) Wsh4[i] = W4[i];
    }

    // stage A transposed: Ash[k][n] = concat(x, nsum)[node_base+n][k]
    {
        const float4* nsum4 = reinterpret_cast<const float4*>(g_nsum);
        #pragma unroll
        for (int it = 0; it < 16; it++) {
            int idx = it * NTHR + tid;
            int n = idx & 127;
            int r = idx >> 7;          // k-quad 0..31
            int gn = node_base + n;
            float4 v = make_float4(0.f, 0.f, 0.f, 0.f);
            if (gn < n_nodes)
                v = (r < 16) ? x4[(long long)gn * 16 + r]
                             : nsum4[(long long)gn * 16 + (r - 16)];
            int k0 = 4 * r;
            Ash[(k0 + 0) * 128 + n] = v.x;
            Ash[(k0 + 1) * 128 + n] = v.y;
            Ash[(k0 + 2) * 128 + n] = v.z;
            Ash[(k0 + 3) * 128 + n] = v.w;
        }
    }
    __syncthreads();

    unsigned long long acc[4][4];
    #pragma unroll
    for (int i = 0; i < 4; i++)
        #pragma unroll
        for (int j = 0; j < 4; j++) acc[i][j] = 0ull;

    const unsigned long long* ab =
        reinterpret_cast<const unsigned long long*>(Ash + 8 * ty);
    const float* wb = Wsh + 4 * tx;

    #pragma unroll 8
    for (int k = 0; k < 128; k++) {
        ulonglong2 a01 = *reinterpret_cast<const ulonglong2*>(ab + k * 64);
        ulonglong2 a23 = *reinterpret_cast<const ulonglong2*>(ab + k * 64 + 2);
        float4 wv = *reinterpret_cast<const float4*>(wb + k * 64);
        unsigned long long wd[4];
        asm("mov.b64 %0, {%1, %1};" : "=l"(wd[0]) : "f"(wv.x));
        asm("mov.b64 %0, {%1, %1};" : "=l"(wd[1]) : "f"(wv.y));
        asm("mov.b64 %0, {%1, %1};" : "=l"(wd[2]) : "f"(wv.z));
        asm("mov.b64 %0, {%1, %1};" : "=l"(wd[3]) : "f"(wv.w));
        unsigned long long ap[4] = {a01.x, a01.y, a23.x, a23.y};
        #pragma unroll
        for (int i = 0; i < 4; i++) {
            asm("fma.rn.f32x2 %0, %1, %2, %0;" : "+l"(acc[i][0]) : "l"(ap[i]), "l"(wd[0]));
            asm("fma.rn.f32x2 %0, %1, %2, %0;" : "+l"(acc[i][1]) : "l"(ap[i]), "l"(wd[1]));
            asm("fma.rn.f32x2 %0, %1, %2, %0;" : "+l"(acc[i][2]) : "l"(ap[i]), "l"(wd[2]));
            asm("fma.rn.f32x2 %0, %1, %2, %0;" : "+l"(acc[i][3]) : "l"(ap[i]), "l"(wd[3]));
        }
    }

    // epilogue: unpack, bias + LayerNorm + store
    const float4 bj = reinterpret_cast<const float4*>(b)[tx];
    const float4 gj = reinterpret_cast<const float4*>(gamma)[tx];
    const float4 ej = reinterpret_cast<const float4*>(beta)[tx];
    const float bja[4] = {bj.x, bj.y, bj.z, bj.w};

    float val[8][4];
    #pragma unroll
    for (int i = 0; i < 4; i++)
        #pragma unroll
        for (int j = 0; j < 4; j++) {
            val[2 * i][j]     = __uint_as_float((unsigned)(acc[i][j] & 0xffffffffull)) + bja[j];
            val[2 * i + 1][j] = __uint_as_float((unsigned)(acc[i][j] >> 32))           + bja[j];
        }

    float s[8], ss[8];
    #pragma unroll
    for (int i = 0; i < 8; i++) {
        s[i]  = val[i][0] + val[i][1] + val[i][2] + val[i][3];
        ss[i] = val[i][0] * val[i][0] + val[i][1] * val[i][1]
              + val[i][2] * val[i][2] + val[i][3] * val[i][3];
    }
    #pragma unroll
    for (int m = 1; m < 16; m <<= 1) {
        #pragma unroll
        for (int i = 0; i < 8; i++) {
            s[i]  += __shfl_xor_sync(0xFFFFFFFFu, s[i],  m);
            ss[i] += __shfl_xor_sync(0xFFFFFFFFu, ss[i], m);
        }
    }

    const float inv64 = 1.0f / 64.0f;
    #pragma unroll
    for (int i = 0; i < 8; i++) {
        float mu  = s[i] * inv64;
        float var = ss[i] * inv64 - mu * mu;
        float rs  = rsqrtf(var + LN_EPS);
        int gn = node_base + 8 * ty + i;
        if (gn < n_nodes) {
            float4 o;
            o.x = (val[i][0] - mu) * rs * gj.x + ej.x;
            o.y = (val[i][1] - mu) * rs * gj.y + ej.y;
            o.z = (val[i][2] - mu) * rs * gj.z + ej.z;
            o.w = (val[i][3] - mu) * rs * gj.w + ej.w;
            out4[(long long)gn * 16 + tx] = o;
        }
    }
}

// ---------------------------------------------------------------------------
// launch
// ---------------------------------------------------------------------------
extern "C" void kernel_launch(void* const* d_in, const int* in_sizes, int n_in,
                              void* d_out, int out_size) {
    const float* x     = (const float*)d_in[0];
    const void*  ei    = d_in[1];
    const float* W     = (const float*)d_in[2];
    const float* b     = (const float*)d_in[3];
    const float* gamma = (const float*)d_in[4];
    const float* beta  = (const float*)d_in[5];
    float* out = (float*)d_out;

    const int n_nodes = in_sizes[0] / D;      // 100000
    const int n_edges = in_sizes[1] / 2;      // 1000000

    static void* nsum_ptr = nullptr;
    if (!nsum_ptr) {
        cudaGetSymbolAddress(&nsum_ptr, g_nsum);
        cudaFuncSetAttribute(gemm_ln_kernel,
                             cudaFuncAttributeMaxDynamicSharedMemorySize, 98304);
    }

    // 0: zero accumulator via memset node
    cudaMemsetAsync(nsum_ptr, 0, (size_t)n_nodes * D * sizeof(float), 0);

    // 1: scatter (chunked unroll-4, vectorized index loads)
    scatter_kernel<<<2368, 256>>>((const float4*)x, ei, n_edges, n_nodes);

    // 2: fused GEMM + LayerNorm (R8-proven)
    int gemm_blocks = (n_nodes + TILE_N - 1) / TILE_N;
    gemm_ln_kernel<<<gemm_blocks, NTHR, 98304>>>(
        (const float4*)x, W, b, gamma, beta, (float4*)out, n_nodes);
}